// round 12
// baseline (speedup 1.0000x reference)
#include <cuda_runtime.h>
#include <math.h>

// Problem constants
#define BATCH   2
#define SEQ     2048
#define CDIM    1024
#define HEADS   16
#define DH      64
#define MLPD    4096
#define RLORA   4
#define TOK     (BATCH * SEQ)          // 4096 token rows
#define QKVD    (3 * CDIM)             // 3072

// ---------------- scratch (static device allocations; no cudaMalloc) --------
__device__ float g_x[TOK * CDIM];        // residual stream
__device__ float g_h[TOK * CDIM];        // layernorm output
__device__ float g_qkv[TOK * QKVD];      // qkv projections
__device__ float g_afterA[TOK * 8];      // lora intermediate
__device__ float g_attn[TOK * CDIM];     // attention output (pre-proj)
__device__ float g_tmp[TOK * CDIM];      // proj / ffn2 output
__device__ float g_mlp[TOK * MLPD];      // ffn hidden

// ---------------- elementwise add (float4) -----------------------------------
__global__ void add4_kernel(const float4* __restrict__ a,
                            const float4* __restrict__ b,
                            float4* __restrict__ o, int n4) {
    int i = blockIdx.x * blockDim.x + threadIdx.x;
    if (i < n4) {
        float4 x = a[i], y = b[i];
        o[i] = make_float4(x.x + y.x, x.y + y.y, x.z + y.z, x.w + y.w);
    }
}

// ---------------- fused residual-add + layernorm ------------------------------
__global__ void __launch_bounds__(256)
add_ln_kernel(const float4* __restrict__ a, const float4* __restrict__ b,
              float4* __restrict__ xout, float4* __restrict__ hout,
              const float4* __restrict__ gg, const float4* __restrict__ bb) {
    int row = blockIdx.x;
    int tid = threadIdx.x;
    size_t idx = (size_t)row * 256 + tid;

    float4 va = a[idx], vb = b[idx];
    float4 v = make_float4(va.x + vb.x, va.y + vb.y, va.z + vb.z, va.w + vb.w);
    xout[idx] = v;

    float s  = v.x + v.y + v.z + v.w;
    float s2 = v.x * v.x + v.y * v.y + v.z * v.z + v.w * v.w;

    __shared__ float red[16];
    #pragma unroll
    for (int o = 16; o; o >>= 1) {
        s  += __shfl_xor_sync(0xffffffffu, s, o);
        s2 += __shfl_xor_sync(0xffffffffu, s2, o);
    }
    int wid = tid >> 5, lid = tid & 31;
    if (lid == 0) { red[wid] = s; red[wid + 8] = s2; }
    __syncthreads();
    if (wid == 0) {
        s  = (lid < 8) ? red[lid] : 0.f;
        s2 = (lid < 8) ? red[lid + 8] : 0.f;
        #pragma unroll
        for (int o = 4; o; o >>= 1) {
            s  += __shfl_xor_sync(0xffffffffu, s, o);
            s2 += __shfl_xor_sync(0xffffffffu, s2, o);
        }
        if (lid == 0) { red[0] = s; red[1] = s2; }
    }
    __syncthreads();
    float mean = red[0] * (1.f / CDIM);
    float var  = red[1] * (1.f / CDIM) - mean * mean;
    float rstd = rsqrtf(var + 1e-5f);

    float4 g4 = gg[tid], b4 = bb[tid];
    float4 h4 = make_float4((v.x - mean) * rstd * g4.x + b4.x,
                            (v.y - mean) * rstd * g4.y + b4.y,
                            (v.z - mean) * rstd * g4.z + b4.z,
                            (v.w - mean) * rstd * g4.w + b4.w);
    hout[idx] = h4;
}

// ---------------- tf32 helpers ------------------------------------------------
__device__ __forceinline__ unsigned f2tf32(float x) {
    unsigned r;
    asm("cvt.rna.tf32.f32 %0, %1;" : "=r"(r) : "f"(x));
    return r;
}

__device__ __forceinline__ void mma_tf32(float* d, const unsigned* a, const unsigned* b) {
    asm volatile(
        "mma.sync.aligned.m16n8k8.row.col.f32.tf32.tf32.f32 "
        "{%0,%1,%2,%3}, {%4,%5,%6,%7}, {%8,%9}, {%0,%1,%2,%3};"
        : "+f"(d[0]), "+f"(d[1]), "+f"(d[2]), "+f"(d[3])
        : "r"(a[0]), "r"(a[1]), "r"(a[2]), "r"(a[3]), "r"(b[0]), "r"(b[1]));
}

__device__ __forceinline__ void cp16(void* smem_dst, const void* gmem_src) {
    unsigned dst = (unsigned)__cvta_generic_to_shared(smem_dst);
    asm volatile("cp.async.cg.shared.global [%0], [%1], 16;" :: "r"(dst), "l"(gmem_src));
}
__device__ __forceinline__ void cp_commit() {
    asm volatile("cp.async.commit_group;");
}
template <int N>
__device__ __forceinline__ void cp_wait() {
    asm volatile("cp.async.wait_group %0;" :: "n"(N));
}

// ---------------- tf32 (3x-split) NT GEMM: out[M,N] = A[M,K] @ W[N,K]^T + bias
// Block tile 128(M) x 64(N), K chunk 32, cp.async double-buffered.
// 8 warps in 4(m) x 2(n), warp tile 32x32. EPI: 0 = none, 1 = exact GELU
#define KPAD 36
template <int EPI>
__global__ void __launch_bounds__(256)
gemm_tf32_kernel(const float* __restrict__ A, const float* __restrict__ W,
                 const float* __restrict__ bias, float* __restrict__ out,
                 int M, int N, int K) {
    __shared__ __align__(16) float As[2][128][KPAD];
    __shared__ __align__(16) float Bs[2][64][KPAD];

    const int tid = threadIdx.x;
    const int wid = tid >> 5;
    const int lane = tid & 31;
    const int g   = lane >> 2;      // group id 0..7
    const int tig = lane & 3;       // thread in group 0..3
    const int warp_m = wid & 3;     // 0..3
    const int warp_n = wid >> 2;    // 0..1
    const int mbase = warp_m * 32;
    const int nbase = warp_n * 32;
    const int bm = blockIdx.y * 128;
    const int bn = blockIdx.x * 64;

    const int arow0 = tid >> 3;
    const int ac4   = (tid & 7) * 4;

    float acc[2][4][4];
    #pragma unroll
    for (int i = 0; i < 2; i++)
        #pragma unroll
        for (int j = 0; j < 4; j++)
            #pragma unroll
            for (int l = 0; l < 4; l++) acc[i][j][l] = 0.f;

    const int NK = K >> 5;   // number of 32-wide K chunks

    auto issue = [&](int ks) {
        int st = ks & 1;
        int k0 = ks << 5;
        #pragma unroll
        for (int it = 0; it < 4; it++) {
            int row = arow0 + it * 32;
            cp16(&As[st][row][ac4], A + (size_t)(bm + row) * K + k0 + ac4);
        }
        #pragma unroll
        for (int it = 0; it < 2; it++) {
            int row = arow0 + it * 32;
            cp16(&Bs[st][row][ac4], W + (size_t)(bn + row) * K + k0 + ac4);
        }
        cp_commit();
    };

    issue(0);
    if (NK > 1) issue(1);

    for (int ks = 0; ks < NK; ks++) {
        if (ks + 1 < NK) cp_wait<1>(); else cp_wait<0>();
        __syncthreads();

        const int st = ks & 1;
        #pragma unroll
        for (int kk = 0; kk < 32; kk += 8) {
            unsigned Abig[2][4], Asml[2][4];
            #pragma unroll
            for (int mf = 0; mf < 2; mf++) {
                int r0 = mbase + mf * 16 + g;
                #pragma unroll
                for (int i = 0; i < 4; i++) {
                    int row = r0 + (i & 1) * 8;
                    int col = kk + (i >> 1) * 4 + tig;
                    float x = As[st][row][col];
                    unsigned bgi = f2tf32(x);
                    Abig[mf][i] = bgi;
                    Asml[mf][i] = f2tf32(x - __uint_as_float(bgi));
                }
            }
            unsigned Bbig[4][2], Bsml[4][2];
            #pragma unroll
            for (int nf = 0; nf < 4; nf++) {
                int n0 = nbase + nf * 8 + g;
                #pragma unroll
                for (int i = 0; i < 2; i++) {
                    int col = kk + i * 4 + tig;
                    float x = Bs[st][n0][col];
                    unsigned bgi = f2tf32(x);
                    Bbig[nf][i] = bgi;
                    Bsml[nf][i] = f2tf32(x - __uint_as_float(bgi));
                }
            }
            #pragma unroll
            for (int mf = 0; mf < 2; mf++)
                #pragma unroll
                for (int nf = 0; nf < 4; nf++) {
                    float* d = acc[mf][nf];
                    mma_tf32(d, Abig[mf], Bbig[nf]);
                    mma_tf32(d, Abig[mf], Bsml[nf]);
                    mma_tf32(d, Asml[mf], Bbig[nf]);
                }
        }
        __syncthreads();
        if (ks + 2 < NK) issue(ks + 2);
    }

    #pragma unroll
    for (int mf = 0; mf < 2; mf++) {
        int r0 = bm + mbase + mf * 16 + g;
        #pragma unroll
        for (int nf = 0; nf < 4; nf++) {
            int col = bn + nbase + nf * 8 + tig * 2;
            float b0 = bias[col], b1 = bias[col + 1];
            #pragma unroll
            for (int half = 0; half < 2; half++) {
                int r = r0 + half * 8;
                float v0 = acc[mf][nf][half * 2 + 0] + b0;
                float v1 = acc[mf][nf][half * 2 + 1] + b1;
                if (EPI == 1) {
                    v0 = 0.5f * v0 * (1.f + erff(v0 * 0.70710678118654752f));
                    v1 = 0.5f * v1 * (1.f + erff(v1 * 0.70710678118654752f));
                }
                *(float2*)(out + (size_t)r * N + col) = make_float2(v0, v1);
            }
        }
    }
}

// ---------------- LoRA: after_A[row, r] = h[row,:] . lora_A[r,:] -------------
__global__ void lora_afterA_kernel(const float* __restrict__ h,
                                   const float* __restrict__ lA,
                                   float* __restrict__ out) {
    int row = blockIdx.x;
    int wid = threadIdx.x >> 5;     // 8 warps -> r = wid
    int lid = threadIdx.x & 31;
    const float* hr = h + (size_t)row * CDIM;
    const float* ar = lA + (size_t)wid * CDIM;
    float s = 0.f;
    for (int c = lid; c < CDIM; c += 32) s += hr[c] * ar[c];
    #pragma unroll
    for (int o = 16; o; o >>= 1) s += __shfl_xor_sync(0xffffffffu, s, o);
    if (lid == 0) out[row * 8 + wid] = s;
}

// ---------------- LoRA apply: qkv[:, :C] += dq, qkv[:, 2C:] += dv ------------
__global__ void lora_apply_kernel(const float* __restrict__ afterA,
                                  const float* __restrict__ lB,
                                  float* __restrict__ qkv) {
    int row = blockIdx.x;
    const float* a = afterA + row * 8;
    float a0 = a[0], a1 = a[1], a2 = a[2], a3 = a[3];
    float a4 = a[4], a5 = a[5], a6 = a[6], a7 = a[7];
    const float scale = 1.f / RLORA;
    for (int c = threadIdx.x; c < CDIM; c += blockDim.x) {
        const float* bq = lB + (size_t)c * RLORA;
        float dq = (a0 * bq[0] + a1 * bq[1] + a2 * bq[2] + a3 * bq[3]) * scale;
        const float* bv = lB + (size_t)(CDIM + c) * RLORA;
        float dv = (a4 * bv[0] + a5 * bv[1] + a6 * bv[2] + a7 * bv[3]) * scale;
        qkv[(size_t)row * QKVD + c]            += dq;
        qkv[(size_t)row * QKVD + 2 * CDIM + c] += dv;
    }
}

// ---------------- tensor-core flash attention (3xTF32 mma, online softmax) ----
// grid: (B*H, SEQ/64). block: 128 threads = 4 warps; warp w owns q-rows
// [64*blockIdx.y + 16w, +16). KV tiles of 32, cp.async double-buffered.
// S and PV both via m16n8k8 tf32 with 3x big/small split.
#define KVT 32
__global__ void __launch_bounds__(128)
attn_mma_kernel(const float* __restrict__ qkv, float* __restrict__ out) {
    __shared__ __align__(16) float Ks[2][KVT][68];   // [buf][kv][dh]
    __shared__ __align__(16) float Vs[2][KVT][72];   // [buf][kv][dh]
    __shared__ __align__(16) float Ps[64][KPAD];     // [q(64)][kv(32)] warp-private rows

    const int b  = blockIdx.x >> 4;
    const int hh = blockIdx.x & 15;
    const int q0 = blockIdx.y * 64;
    const int tid = threadIdx.x;
    const int w   = tid >> 5;
    const int lane = tid & 31;
    const int g   = lane >> 2;
    const int tig = lane & 3;

    const float* base = qkv + (size_t)b * SEQ * QKVD + hh * DH;

    // staging coordinates (shared by K and V tiles)
    const int srr = tid >> 4;            // 0..7  (+8 per iter)
    const int scc = (tid & 15) * 4;      // 0..60

    auto issue_kv = [&](int t) {
        int st = t & 1;
        int kv0 = t * KVT;
        #pragma unroll
        for (int it = 0; it < 4; it++) {
            int rr = srr + it * 8;
            const float* kp = base + (size_t)(kv0 + rr) * QKVD + CDIM + scc;
            const float* vp = base + (size_t)(kv0 + rr) * QKVD + 2 * CDIM + scc;
            cp16(&Ks[st][rr][scc], kp);
            cp16(&Vs[st][rr][scc], vp);
        }
        cp_commit();
    };

    // ---- Q fragments in registers, pre-scaled by 2^-3 (exact), 3x split
    unsigned Qbig[8][4], Qsml[8][4];
    {
        const int r0 = q0 + w * 16 + g;
        #pragma unroll
        for (int kk = 0; kk < 8; kk++) {
            #pragma unroll
            for (int i = 0; i < 4; i++) {
                int row = r0 + (i & 1) * 8;
                int col = kk * 8 + (i >> 1) * 4 + tig;
                float x = base[(size_t)row * QKVD + col] * 0.125f;
                unsigned bgi = f2tf32(x);
                Qbig[kk][i] = bgi;
                Qsml[kk][i] = f2tf32(x - __uint_as_float(bgi));
            }
        }
    }

    float Oacc[8][4];
    #pragma unroll
    for (int nf = 0; nf < 8; nf++)
        #pragma unroll
        for (int i = 0; i < 4; i++) Oacc[nf][i] = 0.f;
    float mrow[2] = {-1e30f, -1e30f};
    float lrow[2] = {0.f, 0.f};

    const int NT = SEQ / KVT;   // 64
    issue_kv(0);

    for (int t = 0; t < NT; t++) {
        if (t + 1 < NT) { issue_kv(t + 1); cp_wait<1>(); }
        else            { cp_wait<0>(); }
        __syncthreads();           // tile t resident for all warps
        const int st = t & 1;

        // ---- S = Q K^T (rows: warp's 16 q, cols: 32 kv), 3xTF32
        float Sacc[4][4];
        #pragma unroll
        for (int nf = 0; nf < 4; nf++)
            #pragma unroll
            for (int i = 0; i < 4; i++) Sacc[nf][i] = 0.f;
        #pragma unroll
        for (int kk = 0; kk < 8; kk++) {
            #pragma unroll
            for (int nf = 0; nf < 4; nf++) {
                unsigned Kbig[2], Ksml[2];
                #pragma unroll
                for (int i = 0; i < 2; i++) {
                    float x = Ks[st][nf * 8 + g][kk * 8 + i * 4 + tig];
                    unsigned bgi = f2tf32(x);
                    Kbig[i] = bgi;
                    Ksml[i] = f2tf32(x - __uint_as_float(bgi));
                }
                mma_tf32(Sacc[nf], Qbig[kk], Kbig);
                mma_tf32(Sacc[nf], Qbig[kk], Ksml);
                mma_tf32(Sacc[nf], Qsml[kk], Kbig);
            }
        }

        // ---- online softmax per row half (rows g and g+8 of the warp tile)
        #pragma unroll
        for (int r = 0; r < 2; r++) {
            float mx = fmaxf(fmaxf(Sacc[0][2 * r], Sacc[0][2 * r + 1]),
                             fmaxf(Sacc[1][2 * r], Sacc[1][2 * r + 1]));
            mx = fmaxf(mx, fmaxf(fmaxf(Sacc[2][2 * r], Sacc[2][2 * r + 1]),
                                 fmaxf(Sacc[3][2 * r], Sacc[3][2 * r + 1])));
            mx = fmaxf(mx, __shfl_xor_sync(0xffffffffu, mx, 1));
            mx = fmaxf(mx, __shfl_xor_sync(0xffffffffu, mx, 2));
            float mnew = fmaxf(mrow[r], mx);
            float corr = __expf(mrow[r] - mnew);
            float psum = 0.f;
            #pragma unroll
            for (int nf = 0; nf < 4; nf++) {
                float p0 = __expf(Sacc[nf][2 * r]     - mnew);
                float p1 = __expf(Sacc[nf][2 * r + 1] - mnew);
                Sacc[nf][2 * r]     = p0;
                Sacc[nf][2 * r + 1] = p1;
                psum += p0 + p1;
            }
            psum += __shfl_xor_sync(0xffffffffu, psum, 1);
            psum += __shfl_xor_sync(0xffffffffu, psum, 2);
            lrow[r] = lrow[r] * corr + psum;
            mrow[r] = mnew;
            #pragma unroll
            for (int nf = 0; nf < 8; nf++) {
                Oacc[nf][2 * r]     *= corr;
                Oacc[nf][2 * r + 1] *= corr;
            }
        }

        // ---- P -> smem (per-warp-private rows), reload as A fragments
        #pragma unroll
        for (int nf = 0; nf < 4; nf++) {
            #pragma unroll
            for (int r = 0; r < 2; r++) {
                *(float2*)&Ps[w * 16 + g + 8 * r][nf * 8 + tig * 2] =
                    make_float2(Sacc[nf][2 * r], Sacc[nf][2 * r + 1]);
            }
        }
        __syncwarp();

        // ---- O += P V, 3xTF32 (K dim = 32 kv -> 4 k-steps)
        #pragma unroll
        for (int kk = 0; kk < 4; kk++) {
            unsigned Pbig[4], Psml[4];
            #pragma unroll
            for (int i = 0; i < 4; i++) {
                int row = w * 16 + g + (i & 1) * 8;
                int col = kk * 8 + (i >> 1) * 4 + tig;
                float x = Ps[row][col];
                unsigned bgi = f2tf32(x);
                Pbig[i] = bgi;
                Psml[i] = f2tf32(x - __uint_as_float(bgi));
            }
            #pragma unroll
            for (int nf = 0; nf < 8; nf++) {
                unsigned Vbig[2], Vsml[2];
                #pragma unroll
                for (int i = 0; i < 2; i++) {
                    float x = Vs[st][kk * 8 + i * 4 + tig][nf * 8 + g];
                    unsigned bgi = f2tf32(x);
                    Vbig[i] = bgi;
                    Vsml[i] = f2tf32(x - __uint_as_float(bgi));
                }
                mma_tf32(Oacc[nf], Pbig, Vbig);
                mma_tf32(Oacc[nf], Pbig, Vsml);
                mma_tf32(Oacc[nf], Psml, Vbig);
            }
        }
        __syncthreads();           // all warps done with buffer st before refill
    }

    // ---- epilogue: divide by l, write [tok][C] at head offset
    float inv0 = 1.f / lrow[0];
    float inv1 = 1.f / lrow[1];
    #pragma unroll
    for (int r = 0; r < 2; r++) {
        int row = q0 + w * 16 + g + 8 * r;
        float inv = r ? inv1 : inv0;
        float* op = out + (size_t)(b * SEQ + row) * CDIM + hh * DH;
        #pragma unroll
        for (int nf = 0; nf < 8; nf++) {
            *(float2*)(op + nf * 8 + tig * 2) =
                make_float2(Oacc[nf][2 * r] * inv, Oacc[nf][2 * r + 1] * inv);
        }
    }
}

// ---------------- launcher ----------------------------------------------------
extern "C" void kernel_launch(void* const* d_in, const int* in_sizes, int n_in,
                              void* d_out, int out_size) {
    const float* x      = (const float*)d_in[0];
    const float* pos    = (const float*)d_in[1];
    const float* Wqkv   = (const float*)d_in[2];
    const float* b_qkv  = (const float*)d_in[3];
    const float* lora_A = (const float*)d_in[4];
    const float* lora_B = (const float*)d_in[5];
    const float* Wproj  = (const float*)d_in[6];
    const float* b_proj = (const float*)d_in[7];
    const float* ln1_g  = (const float*)d_in[8];
    const float* ln1_b  = (const float*)d_in[9];
    const float* ln2_g  = (const float*)d_in[10];
    const float* ln2_b  = (const float*)d_in[11];
    const float* W1     = (const float*)d_in[12];
    const float* b1     = (const float*)d_in[13];
    const float* W2     = (const float*)d_in[14];
    const float* b2     = (const float*)d_in[15];

    float *gx, *gh, *gqkv, *gaA, *gattn, *gtmp, *gmlp;
    cudaGetSymbolAddress((void**)&gx,    g_x);
    cudaGetSymbolAddress((void**)&gh,    g_h);
    cudaGetSymbolAddress((void**)&gqkv,  g_qkv);
    cudaGetSymbolAddress((void**)&gaA,   g_afterA);
    cudaGetSymbolAddress((void**)&gattn, g_attn);
    cudaGetSymbolAddress((void**)&gtmp,  g_tmp);
    cudaGetSymbolAddress((void**)&gmlp,  g_mlp);

    const int n4 = TOK * CDIM / 4;
    const int TB = 256;

    // 1. fused (x + pos) -> g_x, LN1 -> g_h
    add_ln_kernel<<<TOK, 256>>>((const float4*)x, (const float4*)pos,
                                (float4*)gx, (float4*)gh,
                                (const float4*)ln1_g, (const float4*)ln1_b);
    // 2. qkv GEMM
    gemm_tf32_kernel<0><<<dim3(QKVD / 64, TOK / 128), 256>>>(gh, Wqkv, b_qkv, gqkv,
                                                             TOK, QKVD, CDIM);
    // 3-4. LoRA
    lora_afterA_kernel<<<TOK, 256>>>(gh, lora_A, gaA);
    lora_apply_kernel<<<TOK, 256>>>(gaA, lora_B, gqkv);
    // 5. attention (tensor-core 3xTF32 flash, double-buffered KV)
    attn_mma_kernel<<<dim3(BATCH * HEADS, SEQ / 64), 128>>>(gqkv, gattn);
    // 6. output projection
    gemm_tf32_kernel<0><<<dim3(CDIM / 64, TOK / 128), 256>>>(gattn, Wproj, b_proj, gtmp,
                                                             TOK, CDIM, CDIM);
    // 7. fused residual add -> g_x, LN2 -> g_h
    add_ln_kernel<<<TOK, 256>>>((const float4*)gx, (const float4*)gtmp,
                                (float4*)gx, (float4*)gh,
                                (const float4*)ln2_g, (const float4*)ln2_b);
    // 8. FFN1 + GELU
    gemm_tf32_kernel<1><<<dim3(MLPD / 64, TOK / 128), 256>>>(gh, W1, b1, gmlp,
                                                             TOK, MLPD, CDIM);
    // 9. FFN2
    gemm_tf32_kernel<0><<<dim3(CDIM / 64, TOK / 128), 256>>>(gmlp, W2, b2, gtmp,
                                                             TOK, CDIM, MLPD);
    // 10. final residual -> output
    add4_kernel<<<(n4 + TB - 1) / TB, TB>>>((const float4*)gx, (const float4*)gtmp,
                                            (float4*)d_out, n4);
}

// round 14
// speedup vs baseline: 1.2984x; 1.2984x over previous
#include <cuda_runtime.h>
#include <math.h>

// Problem constants
#define BATCH   2
#define SEQ     2048
#define CDIM    1024
#define HEADS   16
#define DH      64
#define MLPD    4096
#define RLORA   4
#define TOK     (BATCH * SEQ)          // 4096 token rows
#define QKVD    (3 * CDIM)             // 3072

// ---------------- scratch (static device allocations; no cudaMalloc) --------
__device__ float g_x[TOK * CDIM];        // residual stream
__device__ float g_h[TOK * CDIM];        // layernorm output
__device__ float g_qkv[TOK * QKVD];      // qkv projections
__device__ float g_afterA[TOK * 8];      // lora intermediate
__device__ float g_attn[TOK * CDIM];     // attention output (pre-proj)
__device__ float g_tmp[TOK * CDIM];      // proj / ffn2 output
__device__ float g_mlp[TOK * MLPD];      // ffn hidden

// ---------------- elementwise add (float4) -----------------------------------
__global__ void add4_kernel(const float4* __restrict__ a,
                            const float4* __restrict__ b,
                            float4* __restrict__ o, int n4) {
    int i = blockIdx.x * blockDim.x + threadIdx.x;
    if (i < n4) {
        float4 x = a[i], y = b[i];
        o[i] = make_float4(x.x + y.x, x.y + y.y, x.z + y.z, x.w + y.w);
    }
}

// ---------------- fused residual-add + layernorm ------------------------------
__global__ void __launch_bounds__(256)
add_ln_kernel(const float4* __restrict__ a, const float4* __restrict__ b,
              float4* __restrict__ xout, float4* __restrict__ hout,
              const float4* __restrict__ gg, const float4* __restrict__ bb) {
    int row = blockIdx.x;
    int tid = threadIdx.x;
    size_t idx = (size_t)row * 256 + tid;

    float4 va = a[idx], vb = b[idx];
    float4 v = make_float4(va.x + vb.x, va.y + vb.y, va.z + vb.z, va.w + vb.w);
    xout[idx] = v;

    float s  = v.x + v.y + v.z + v.w;
    float s2 = v.x * v.x + v.y * v.y + v.z * v.z + v.w * v.w;

    __shared__ float red[16];
    #pragma unroll
    for (int o = 16; o; o >>= 1) {
        s  += __shfl_xor_sync(0xffffffffu, s, o);
        s2 += __shfl_xor_sync(0xffffffffu, s2, o);
    }
    int wid = tid >> 5, lid = tid & 31;
    if (lid == 0) { red[wid] = s; red[wid + 8] = s2; }
    __syncthreads();
    if (wid == 0) {
        s  = (lid < 8) ? red[lid] : 0.f;
        s2 = (lid < 8) ? red[lid + 8] : 0.f;
        #pragma unroll
        for (int o = 4; o; o >>= 1) {
            s  += __shfl_xor_sync(0xffffffffu, s, o);
            s2 += __shfl_xor_sync(0xffffffffu, s2, o);
        }
        if (lid == 0) { red[0] = s; red[1] = s2; }
    }
    __syncthreads();
    float mean = red[0] * (1.f / CDIM);
    float var  = red[1] * (1.f / CDIM) - mean * mean;
    float rstd = rsqrtf(var + 1e-5f);

    float4 g4 = gg[tid], b4 = bb[tid];
    float4 h4 = make_float4((v.x - mean) * rstd * g4.x + b4.x,
                            (v.y - mean) * rstd * g4.y + b4.y,
                            (v.z - mean) * rstd * g4.z + b4.z,
                            (v.w - mean) * rstd * g4.w + b4.w);
    hout[idx] = h4;
}

// ---------------- tf32 helpers (attention path) --------------------------------
__device__ __forceinline__ unsigned f2tf32(float x) {
    unsigned r;
    asm("cvt.rna.tf32.f32 %0, %1;" : "=r"(r) : "f"(x));
    return r;
}

__device__ __forceinline__ void mma_tf32(float* d, const unsigned* a, const unsigned* b) {
    asm volatile(
        "mma.sync.aligned.m16n8k8.row.col.f32.tf32.tf32.f32 "
        "{%0,%1,%2,%3}, {%4,%5,%6,%7}, {%8,%9}, {%0,%1,%2,%3};"
        : "+f"(d[0]), "+f"(d[1]), "+f"(d[2]), "+f"(d[3])
        : "r"(a[0]), "r"(a[1]), "r"(a[2]), "r"(a[3]), "r"(b[0]), "r"(b[1]));
}

// ---------------- bf16 split helpers (GEMM path) --------------------------------
// x = hi + lo with hi = rn_bf16(x); x - hi exact (two-sum); products exact in fp32.
__device__ __forceinline__ void split_bf16(float x0, float x1,
                                           unsigned& hi, unsigned& lo) {
    unsigned h;
    asm("cvt.rn.bf16x2.f32 %0, %1, %2;" : "=r"(h) : "f"(x1), "f"(x0));  // low=x0, high=x1
    float h0 = __uint_as_float(h << 16);
    float h1 = __uint_as_float(h & 0xFFFF0000u);
    unsigned l;
    asm("cvt.rn.bf16x2.f32 %0, %1, %2;" : "=r"(l) : "f"(x1 - h1), "f"(x0 - h0));
    hi = h; lo = l;
}

__device__ __forceinline__ void mma_bf16(float* d, const unsigned* a, const unsigned* b) {
    asm volatile(
        "mma.sync.aligned.m16n8k16.row.col.f32.bf16.bf16.f32 "
        "{%0,%1,%2,%3}, {%4,%5,%6,%7}, {%8,%9}, {%0,%1,%2,%3};"
        : "+f"(d[0]), "+f"(d[1]), "+f"(d[2]), "+f"(d[3])
        : "r"(a[0]), "r"(a[1]), "r"(a[2]), "r"(a[3]), "r"(b[0]), "r"(b[1]));
}

__device__ __forceinline__ void cp16(void* smem_dst, const void* gmem_src) {
    unsigned dst = (unsigned)__cvta_generic_to_shared(smem_dst);
    asm volatile("cp.async.cg.shared.global [%0], [%1], 16;" :: "r"(dst), "l"(gmem_src));
}
__device__ __forceinline__ void cp_commit() {
    asm volatile("cp.async.commit_group;");
}
template <int N>
__device__ __forceinline__ void cp_wait() {
    asm volatile("cp.async.wait_group %0;" :: "n"(N));
}

// ---------------- bf16x3 NT GEMM: out[M,N] = A[M,K] @ W[N,K]^T + bias
// Block tile 128(M) x 64(N), K chunk 32, cp.async double-buffered.
// 8 warps in 4(m) x 2(n), warp tile 32x32, mma.m16n8k16.bf16 with
// 3-term error-compensated split (hi*hi + hi*lo + lo*hi; lo*lo ~2^-16 dropped).
// EPI: 0 = none, 1 = exact GELU
#define KPAD 36
template <int EPI>
__global__ void __launch_bounds__(256)
gemm_bf16x3_kernel(const float* __restrict__ A, const float* __restrict__ W,
                   const float* __restrict__ bias, float* __restrict__ out,
                   int M, int N, int K) {
    __shared__ __align__(16) float As[2][128][KPAD];
    __shared__ __align__(16) float Bs[2][64][KPAD];

    const int tid = threadIdx.x;
    const int wid = tid >> 5;
    const int lane = tid & 31;
    const int g   = lane >> 2;      // group id 0..7
    const int tig = lane & 3;       // thread in group 0..3
    const int warp_m = wid & 3;     // 0..3
    const int warp_n = wid >> 2;    // 0..1
    const int mbase = warp_m * 32;
    const int nbase = warp_n * 32;
    const int bm = blockIdx.y * 128;
    const int bn = blockIdx.x * 64;

    const int arow0 = tid >> 3;
    const int ac4   = (tid & 7) * 4;

    float acc[2][4][4];
    #pragma unroll
    for (int i = 0; i < 2; i++)
        #pragma unroll
        for (int j = 0; j < 4; j++)
            #pragma unroll
            for (int l = 0; l < 4; l++) acc[i][j][l] = 0.f;

    const int NK = K >> 5;   // number of 32-wide K chunks

    auto issue = [&](int ks) {
        int st = ks & 1;
        int k0 = ks << 5;
        #pragma unroll
        for (int it = 0; it < 4; it++) {
            int row = arow0 + it * 32;
            cp16(&As[st][row][ac4], A + (size_t)(bm + row) * K + k0 + ac4);
        }
        #pragma unroll
        for (int it = 0; it < 2; it++) {
            int row = arow0 + it * 32;
            cp16(&Bs[st][row][ac4], W + (size_t)(bn + row) * K + k0 + ac4);
        }
        cp_commit();
    };

    issue(0);
    if (NK > 1) issue(1);

    for (int ks = 0; ks < NK; ks++) {
        if (ks + 1 < NK) cp_wait<1>(); else cp_wait<0>();
        __syncthreads();

        const int st = ks & 1;
        #pragma unroll
        for (int kk = 0; kk < 32; kk += 16) {
            // A fragments: m16n8k16, 4 b32 regs each holding 2 bf16 (k pair)
            unsigned Ahi[2][4], Alo[2][4];
            #pragma unroll
            for (int mf = 0; mf < 2; mf++) {
                int r0 = mbase + mf * 16 + g;
                #pragma unroll
                for (int i = 0; i < 4; i++) {
                    int row = r0 + (i & 1) * 8;
                    int col = kk + (i >> 1) * 8 + tig * 2;
                    float2 x = *(const float2*)&As[st][row][col];
                    split_bf16(x.x, x.y, Ahi[mf][i], Alo[mf][i]);
                }
            }
            // B fragments: 2 b32 regs each holding 2 bf16
            unsigned Bhi[4][2], Blo[4][2];
            #pragma unroll
            for (int nf = 0; nf < 4; nf++) {
                int n0 = nbase + nf * 8 + g;
                #pragma unroll
                for (int i = 0; i < 2; i++) {
                    int col = kk + i * 8 + tig * 2;
                    float2 x = *(const float2*)&Bs[st][n0][col];
                    split_bf16(x.x, x.y, Bhi[nf][i], Blo[nf][i]);
                }
            }
            // 3xBF16 mma: hi*hi + hi*lo + lo*hi
            #pragma unroll
            for (int mf = 0; mf < 2; mf++)
                #pragma unroll
                for (int nf = 0; nf < 4; nf++) {
                    float* d = acc[mf][nf];
                    mma_bf16(d, Ahi[mf], Bhi[nf]);
                    mma_bf16(d, Ahi[mf], Blo[nf]);
                    mma_bf16(d, Alo[mf], Bhi[nf]);
                }
        }
        __syncthreads();
        if (ks + 2 < NK) issue(ks + 2);
    }

    #pragma unroll
    for (int mf = 0; mf < 2; mf++) {
        int r0 = bm + mbase + mf * 16 + g;
        #pragma unroll
        for (int nf = 0; nf < 4; nf++) {
            int col = bn + nbase + nf * 8 + tig * 2;
            float b0 = bias[col], b1 = bias[col + 1];
            #pragma unroll
            for (int half = 0; half < 2; half++) {
                int r = r0 + half * 8;
                float v0 = acc[mf][nf][half * 2 + 0] + b0;
                float v1 = acc[mf][nf][half * 2 + 1] + b1;
                if (EPI == 1) {
                    v0 = 0.5f * v0 * (1.f + erff(v0 * 0.70710678118654752f));
                    v1 = 0.5f * v1 * (1.f + erff(v1 * 0.70710678118654752f));
                }
                *(float2*)(out + (size_t)r * N + col) = make_float2(v0, v1);
            }
        }
    }
}

// ---------------- LoRA: after_A[row, r] = h[row,:] . lora_A[r,:] -------------
__global__ void lora_afterA_kernel(const float* __restrict__ h,
                                   const float* __restrict__ lA,
                                   float* __restrict__ out) {
    int row = blockIdx.x;
    int wid = threadIdx.x >> 5;     // 8 warps -> r = wid
    int lid = threadIdx.x & 31;
    const float* hr = h + (size_t)row * CDIM;
    const float* ar = lA + (size_t)wid * CDIM;
    float s = 0.f;
    for (int c = lid; c < CDIM; c += 32) s += hr[c] * ar[c];
    #pragma unroll
    for (int o = 16; o; o >>= 1) s += __shfl_xor_sync(0xffffffffu, s, o);
    if (lid == 0) out[row * 8 + wid] = s;
}

// ---------------- LoRA apply: qkv[:, :C] += dq, qkv[:, 2C:] += dv ------------
__global__ void lora_apply_kernel(const float* __restrict__ afterA,
                                  const float* __restrict__ lB,
                                  float* __restrict__ qkv) {
    int row = blockIdx.x;
    const float* a = afterA + row * 8;
    float a0 = a[0], a1 = a[1], a2 = a[2], a3 = a[3];
    float a4 = a[4], a5 = a[5], a6 = a[6], a7 = a[7];
    const float scale = 1.f / RLORA;
    for (int c = threadIdx.x; c < CDIM; c += blockDim.x) {
        const float* bq = lB + (size_t)c * RLORA;
        float dq = (a0 * bq[0] + a1 * bq[1] + a2 * bq[2] + a3 * bq[3]) * scale;
        const float* bv = lB + (size_t)(CDIM + c) * RLORA;
        float dv = (a4 * bv[0] + a5 * bv[1] + a6 * bv[2] + a7 * bv[3]) * scale;
        qkv[(size_t)row * QKVD + c]            += dq;
        qkv[(size_t)row * QKVD + 2 * CDIM + c] += dv;
    }
}

// ---------------- tensor-core flash attention (3xTF32 mma, online softmax) ----
// grid: (B*H, SEQ/64). block: 128 threads = 4 warps; warp w owns q-rows
// [64*blockIdx.y + 16w, +16). KV tiles of 32, cp.async double-buffered.
// S and PV both via m16n8k8 tf32 with 3x big/small split.
#define KVT 32
__global__ void __launch_bounds__(128)
attn_mma_kernel(const float* __restrict__ qkv, float* __restrict__ out) {
    __shared__ __align__(16) float Ks[2][KVT][68];   // [buf][kv][dh]
    __shared__ __align__(16) float Vs[2][KVT][72];   // [buf][kv][dh]
    __shared__ __align__(16) float Ps[64][KPAD];     // [q(64)][kv(32)] warp-private rows

    const int b  = blockIdx.x >> 4;
    const int hh = blockIdx.x & 15;
    const int q0 = blockIdx.y * 64;
    const int tid = threadIdx.x;
    const int w   = tid >> 5;
    const int lane = tid & 31;
    const int g   = lane >> 2;
    const int tig = lane & 3;

    const float* base = qkv + (size_t)b * SEQ * QKVD + hh * DH;

    // staging coordinates (shared by K and V tiles)
    const int srr = tid >> 4;            // 0..7  (+8 per iter)
    const int scc = (tid & 15) * 4;      // 0..60

    auto issue_kv = [&](int t) {
        int st = t & 1;
        int kv0 = t * KVT;
        #pragma unroll
        for (int it = 0; it < 4; it++) {
            int rr = srr + it * 8;
            const float* kp = base + (size_t)(kv0 + rr) * QKVD + CDIM + scc;
            const float* vp = base + (size_t)(kv0 + rr) * QKVD + 2 * CDIM + scc;
            cp16(&Ks[st][rr][scc], kp);
            cp16(&Vs[st][rr][scc], vp);
        }
        cp_commit();
    };

    // ---- Q fragments in registers, pre-scaled by 2^-3 (exact), 3x split
    unsigned Qbig[8][4], Qsml[8][4];
    {
        const int r0 = q0 + w * 16 + g;
        #pragma unroll
        for (int kk = 0; kk < 8; kk++) {
            #pragma unroll
            for (int i = 0; i < 4; i++) {
                int row = r0 + (i & 1) * 8;
                int col = kk * 8 + (i >> 1) * 4 + tig;
                float x = base[(size_t)row * QKVD + col] * 0.125f;
                unsigned bgi = f2tf32(x);
                Qbig[kk][i] = bgi;
                Qsml[kk][i] = f2tf32(x - __uint_as_float(bgi));
            }
        }
    }

    float Oacc[8][4];
    #pragma unroll
    for (int nf = 0; nf < 8; nf++)
        #pragma unroll
        for (int i = 0; i < 4; i++) Oacc[nf][i] = 0.f;
    float mrow[2] = {-1e30f, -1e30f};
    float lrow[2] = {0.f, 0.f};

    const int NT = SEQ / KVT;   // 64
    issue_kv(0);

    for (int t = 0; t < NT; t++) {
        if (t + 1 < NT) { issue_kv(t + 1); cp_wait<1>(); }
        else            { cp_wait<0>(); }
        __syncthreads();           // tile t resident for all warps
        const int st = t & 1;

        // ---- S = Q K^T (rows: warp's 16 q, cols: 32 kv), 3xTF32
        float Sacc[4][4];
        #pragma unroll
        for (int nf = 0; nf < 4; nf++)
            #pragma unroll
            for (int i = 0; i < 4; i++) Sacc[nf][i] = 0.f;
        #pragma unroll
        for (int kk = 0; kk < 8; kk++) {
            #pragma unroll
            for (int nf = 0; nf < 4; nf++) {
                unsigned Kbig[2], Ksml[2];
                #pragma unroll
                for (int i = 0; i < 2; i++) {
                    float x = Ks[st][nf * 8 + g][kk * 8 + i * 4 + tig];
                    unsigned bgi = f2tf32(x);
                    Kbig[i] = bgi;
                    Ksml[i] = f2tf32(x - __uint_as_float(bgi));
                }
                mma_tf32(Sacc[nf], Qbig[kk], Kbig);
                mma_tf32(Sacc[nf], Qbig[kk], Ksml);
                mma_tf32(Sacc[nf], Qsml[kk], Kbig);
            }
        }

        // ---- online softmax per row half (rows g and g+8 of the warp tile)
        #pragma unroll
        for (int r = 0; r < 2; r++) {
            float mx = fmaxf(fmaxf(Sacc[0][2 * r], Sacc[0][2 * r + 1]),
                             fmaxf(Sacc[1][2 * r], Sacc[1][2 * r + 1]));
            mx = fmaxf(mx, fmaxf(fmaxf(Sacc[2][2 * r], Sacc[2][2 * r + 1]),
                                 fmaxf(Sacc[3][2 * r], Sacc[3][2 * r + 1])));
            mx = fmaxf(mx, __shfl_xor_sync(0xffffffffu, mx, 1));
            mx = fmaxf(mx, __shfl_xor_sync(0xffffffffu, mx, 2));
            float mnew = fmaxf(mrow[r], mx);
            float corr = __expf(mrow[r] - mnew);
            float psum = 0.f;
            #pragma unroll
            for (int nf = 0; nf < 4; nf++) {
                float p0 = __expf(Sacc[nf][2 * r]     - mnew);
                float p1 = __expf(Sacc[nf][2 * r + 1] - mnew);
                Sacc[nf][2 * r]     = p0;
                Sacc[nf][2 * r + 1] = p1;
                psum += p0 + p1;
            }
            psum += __shfl_xor_sync(0xffffffffu, psum, 1);
            psum += __shfl_xor_sync(0xffffffffu, psum, 2);
            lrow[r] = lrow[r] * corr + psum;
            mrow[r] = mnew;
            #pragma unroll
            for (int nf = 0; nf < 8; nf++) {
                Oacc[nf][2 * r]     *= corr;
                Oacc[nf][2 * r + 1] *= corr;
            }
        }

        // ---- P -> smem (per-warp-private rows), reload as A fragments
        #pragma unroll
        for (int nf = 0; nf < 4; nf++) {
            #pragma unroll
            for (int r = 0; r < 2; r++) {
                *(float2*)&Ps[w * 16 + g + 8 * r][nf * 8 + tig * 2] =
                    make_float2(Sacc[nf][2 * r], Sacc[nf][2 * r + 1]);
            }
        }
        __syncwarp();

        // ---- O += P V, 3xTF32 (K dim = 32 kv -> 4 k-steps)
        #pragma unroll
        for (int kk = 0; kk < 4; kk++) {
            unsigned Pbig[4], Psml[4];
            #pragma unroll
            for (int i = 0; i < 4; i++) {
                int row = w * 16 + g + (i & 1) * 8;
                int col = kk * 8 + (i >> 1) * 4 + tig;
                float x = Ps[row][col];
                unsigned bgi = f2tf32(x);
                Pbig[i] = bgi;
                Psml[i] = f2tf32(x - __uint_as_float(bgi));
            }
            #pragma unroll
            for (int nf = 0; nf < 8; nf++) {
                unsigned Vbig[2], Vsml[2];
                #pragma unroll
                for (int i = 0; i < 2; i++) {
                    float x = Vs[st][kk * 8 + i * 4 + tig][nf * 8 + g];
                    unsigned bgi = f2tf32(x);
                    Vbig[i] = bgi;
                    Vsml[i] = f2tf32(x - __uint_as_float(bgi));
                }
                mma_tf32(Oacc[nf], Pbig, Vbig);
                mma_tf32(Oacc[nf], Pbig, Vsml);
                mma_tf32(Oacc[nf], Psml, Vbig);
            }
        }
        __syncthreads();           // all warps done with buffer st before refill
    }

    // ---- epilogue: divide by l, write [tok][C] at head offset
    float inv0 = 1.f / lrow[0];
    float inv1 = 1.f / lrow[1];
    #pragma unroll
    for (int r = 0; r < 2; r++) {
        int row = q0 + w * 16 + g + 8 * r;
        float inv = r ? inv1 : inv0;
        float* op = out + (size_t)(b * SEQ + row) * CDIM + hh * DH;
        #pragma unroll
        for (int nf = 0; nf < 8; nf++) {
            *(float2*)(op + nf * 8 + tig * 2) =
                make_float2(Oacc[nf][2 * r] * inv, Oacc[nf][2 * r + 1] * inv);
        }
    }
}

// ---------------- launcher ----------------------------------------------------
extern "C" void kernel_launch(void* const* d_in, const int* in_sizes, int n_in,
                              void* d_out, int out_size) {
    const float* x      = (const float*)d_in[0];
    const float* pos    = (const float*)d_in[1];
    const float* Wqkv   = (const float*)d_in[2];
    const float* b_qkv  = (const float*)d_in[3];
    const float* lora_A = (const float*)d_in[4];
    const float* lora_B = (const float*)d_in[5];
    const float* Wproj  = (const float*)d_in[6];
    const float* b_proj = (const float*)d_in[7];
    const float* ln1_g  = (const float*)d_in[8];
    const float* ln1_b  = (const float*)d_in[9];
    const float* ln2_g  = (const float*)d_in[10];
    const float* ln2_b  = (const float*)d_in[11];
    const float* W1     = (const float*)d_in[12];
    const float* b1     = (const float*)d_in[13];
    const float* W2     = (const float*)d_in[14];
    const float* b2     = (const float*)d_in[15];

    float *gx, *gh, *gqkv, *gaA, *gattn, *gtmp, *gmlp;
    cudaGetSymbolAddress((void**)&gx,    g_x);
    cudaGetSymbolAddress((void**)&gh,    g_h);
    cudaGetSymbolAddress((void**)&gqkv,  g_qkv);
    cudaGetSymbolAddress((void**)&gaA,   g_afterA);
    cudaGetSymbolAddress((void**)&gattn, g_attn);
    cudaGetSymbolAddress((void**)&gtmp,  g_tmp);
    cudaGetSymbolAddress((void**)&gmlp,  g_mlp);

    const int n4 = TOK * CDIM / 4;
    const int TB = 256;

    // 1. fused (x + pos) -> g_x, LN1 -> g_h
    add_ln_kernel<<<TOK, 256>>>((const float4*)x, (const float4*)pos,
                                (float4*)gx, (float4*)gh,
                                (const float4*)ln1_g, (const float4*)ln1_b);
    // 2. qkv GEMM (bf16x3 tensor cores)
    gemm_bf16x3_kernel<0><<<dim3(QKVD / 64, TOK / 128), 256>>>(gh, Wqkv, b_qkv, gqkv,
                                                               TOK, QKVD, CDIM);
    // 3-4. LoRA
    lora_afterA_kernel<<<TOK, 256>>>(gh, lora_A, gaA);
    lora_apply_kernel<<<TOK, 256>>>(gaA, lora_B, gqkv);
    // 5. attention (tensor-core 3xTF32 flash, double-buffered KV)
    attn_mma_kernel<<<dim3(BATCH * HEADS, SEQ / 64), 128>>>(gqkv, gattn);
    // 6. output projection
    gemm_bf16x3_kernel<0><<<dim3(CDIM / 64, TOK / 128), 256>>>(gattn, Wproj, b_proj, gtmp,
                                                               TOK, CDIM, CDIM);
    // 7. fused residual add -> g_x, LN2 -> g_h
    add_ln_kernel<<<TOK, 256>>>((const float4*)gx, (const float4*)gtmp,
                                (float4*)gx, (float4*)gh,
                                (const float4*)ln2_g, (const float4*)ln2_b);
    // 8. FFN1 + GELU
    gemm_bf16x3_kernel<1><<<dim3(MLPD / 64, TOK / 128), 256>>>(gh, W1, b1, gmlp,
                                                               TOK, MLPD, CDIM);
    // 9. FFN2
    gemm_bf16x3_kernel<0><<<dim3(CDIM / 64, TOK / 128), 256>>>(gmlp, W2, b2, gtmp,
                                                               TOK, CDIM, MLPD);
    // 10. final residual -> output
    add4_kernel<<<(n4 + TB - 1) / TB, TB>>>((const float4*)gx, (const float4*)gtmp,
                                            (float4*)d_out, n4);
}